// round 9
// baseline (speedup 1.0000x reference)
#include <cuda_runtime.h>
#include <math.h>

#define BB 2
#define TT 2048
#define CC 512
#define NB 4
#define QN (NB*CC)   // 2048
#define HALF (CC/2)  // 256

// Scratch (no cudaMalloc allowed)
__device__ float g_Q[BB*TT*QN];
__device__ float g_K[BB*TT*CC];
__device__ float g_V[BB*TT*QN];
__device__ float g_Y[BB*TT*CC];

// ---------------------------------------------------------------------------
// SGEMM (R1 scalar version, known-good): Out[M,N] = A[M,K] @ W[K,N].
// BM=128, BN=64, BK=16, 256 threads, 8x4 per thread. Optional RoPE + scale.
// ---------------------------------------------------------------------------
template<int DO_ROPE>
__global__ void __launch_bounds__(256) gemm_kernel(
    const float* __restrict__ A, const float* __restrict__ W, float* __restrict__ Out,
    int M, int N, int K,
    const float* __restrict__ cosT, const float* __restrict__ sinT, float scale)
{
    constexpr int BM = 128, BN = 64, BK = 16;
    __shared__ float As[BK][BM];
    __shared__ float Ws[BK][BN];

    const int tid = threadIdx.x;
    const int tx = tid & 15;
    const int ty = tid >> 4;
    const int rowBase = blockIdx.y * BM;
    const int colBase = blockIdx.x * BN;

    float acc[8][4];
#pragma unroll
    for (int m = 0; m < 8; m++)
#pragma unroll
        for (int n = 0; n < 4; n++) acc[m][n] = 0.f;

    for (int k0 = 0; k0 < K; k0 += BK) {
#pragma unroll
        for (int i = 0; i < 2; i++) {
            int slot = tid + i * 256;
            int r  = slot >> 2;
            int c4 = (slot & 3) * 4;
            float4 v = *(const float4*)(A + (size_t)(rowBase + r) * K + k0 + c4);
            As[c4 + 0][r] = v.x; As[c4 + 1][r] = v.y;
            As[c4 + 2][r] = v.z; As[c4 + 3][r] = v.w;
        }
        {
            int rr = tid >> 4;
            int c4 = (tid & 15) * 4;
            float4 v = *(const float4*)(W + (size_t)(k0 + rr) * N + colBase + c4);
            *(float4*)&Ws[rr][c4] = v;
        }
        __syncthreads();

#pragma unroll
        for (int kk = 0; kk < BK; kk++) {
            float4 a0 = *(float4*)&As[kk][ty * 8];
            float4 a1 = *(float4*)&As[kk][ty * 8 + 4];
            float4 wv = *(float4*)&Ws[kk][tx * 4];
            float ar[8] = {a0.x, a0.y, a0.z, a0.w, a1.x, a1.y, a1.z, a1.w};
            float wr[4] = {wv.x, wv.y, wv.z, wv.w};
#pragma unroll
            for (int m = 0; m < 8; m++)
#pragma unroll
                for (int n = 0; n < 4; n++) acc[m][n] += ar[m] * wr[n];
        }
        __syncthreads();
    }

    const int gc = colBase + tx * 4;
#pragma unroll
    for (int mI = 0; mI < 8; mI++) {
        int gr = rowBase + ty * 8 + mI;
        float o0 = acc[mI][0], o1 = acc[mI][1], o2 = acc[mI][2], o3 = acc[mI][3];
        if (DO_ROPE) {
            int t   = gr & (TT - 1);
            int cin = gc & (CC - 1);
            int i0  = cin >> 1;
            float c0v = cosT[t * HALF + i0],     s0v = sinT[t * HALF + i0];
            float c1v = cosT[t * HALF + i0 + 1], s1v = sinT[t * HALF + i0 + 1];
            float r0 = o0 * c0v - o1 * s0v;
            float r1 = o0 * s0v + o1 * c0v;
            float r2 = o2 * c1v - o3 * s1v;
            float r3 = o2 * s1v + o3 * c1v;
            o0 = r0; o1 = r1; o2 = r2; o3 = r3;
        }
        float4 out4 = make_float4(o0 * scale, o1 * scale, o2 * scale, o3 * scale);
        *(float4*)(Out + (size_t)gr * N + gc) = out4;
    }
}

// ---------------------------------------------------------------------------
// Fused routed attention, s-per-lane: 1 warp = 1 query row, 8 rows/CTA.
// S tiles of 32; each lane owns one s of the tile: dots are lane-local FFMA
// chains (q via uniform L1 loads, K row from padded smem), argmax/exp are
// lane-local, warp reductions happen ONCE per 32 steps.
// K tile in dynamic smem: [32][129] float4 (row pad kills bank conflicts).
// ---------------------------------------------------------------------------
#define KROW 129   // float4 per padded K row

__global__ void __launch_bounds__(256) attn_kernel(
    const float* __restrict__ Q, const float* __restrict__ K,
    const float* __restrict__ V, float* __restrict__ Y)
{
    extern __shared__ float4 ks4[];   // [32][KROW] = 66,048 B

    const int tid  = threadIdx.x;
    const int w    = tid >> 5;
    const int lane = tid & 31;
    const int r    = blockIdx.x * 8 + w;
    const int t    = r & (TT - 1);
    const int tmax = (blockIdx.x * 8 + 7) & (TT - 1);

    const float4* qp4 = (const float4*)(Q + (size_t)r * QN);
    const float4* kb4 = (const float4*)(K + (size_t)(r - t) * CC);
    const float*  vb  = V + (size_t)(r - t) * QN;

    float4 acc4[4];
#pragma unroll
    for (int jj = 0; jj < 4; jj++) acc4[jj] = make_float4(0.f, 0.f, 0.f, 0.f);
    float m = -1e30f, l = 0.f;

    const int s_ld = tid >> 3;   // 0..31: K row this thread helps load
    const int c_ld = tid & 7;    // chunk within row

    for (int s0 = 0; s0 <= tmax; s0 += 32) {
        // ---- cooperative K tile load: 32 rows x 128 float4 ----
        {
            const float4* krow = kb4 + (size_t)(s0 + s_ld) * 128;
            float4* srow = &ks4[s_ld * KROW];
#pragma unroll
            for (int i = 0; i < 16; i++)
                srow[c_ld + i * 8] = krow[c_ld + i * 8];
        }
        __syncthreads();

        int send = t - s0; if (send > 31) send = 31;
        if (send >= 0) {
            // ---- dots: lane computes scores for s = s0 + lane ----
            float4 d4[NB];
#pragma unroll
            for (int n = 0; n < NB; n++) d4[n] = make_float4(0.f, 0.f, 0.f, 0.f);
            const float4* kr = &ks4[lane * KROW];
#pragma unroll 8
            for (int c4 = 0; c4 < 128; c4++) {
                float4 k4 = kr[c4];
                float4 q0 = qp4[c4];
                float4 q1 = qp4[128 + c4];
                float4 q2 = qp4[256 + c4];
                float4 q3 = qp4[384 + c4];
                d4[0].x += q0.x * k4.x; d4[0].y += q0.y * k4.y;
                d4[0].z += q0.z * k4.z; d4[0].w += q0.w * k4.w;
                d4[1].x += q1.x * k4.x; d4[1].y += q1.y * k4.y;
                d4[1].z += q1.z * k4.z; d4[1].w += q1.w * k4.w;
                d4[2].x += q2.x * k4.x; d4[2].y += q2.y * k4.y;
                d4[2].z += q2.z * k4.z; d4[2].w += q2.w * k4.w;
                d4[3].x += q3.x * k4.x; d4[3].y += q3.y * k4.y;
                d4[3].z += q3.z * k4.z; d4[3].w += q3.w * k4.w;
            }
            float d[NB];
#pragma unroll
            for (int n = 0; n < NB; n++)
                d[n] = (d4[n].x + d4[n].y) + (d4[n].z + d4[n].w);

            // ---- lane-local branch argmax ----
            float smax = d[0]; int nsel = 0;
            if (d[1] > smax) { smax = d[1]; nsel = 1; }
            if (d[2] > smax) { smax = d[2]; nsel = 2; }
            if (d[3] > smax) { smax = d[3]; nsel = 3; }
            if (lane > send) smax = -1e30f;   // mask non-causal lanes

            // ---- once-per-tile online softmax update ----
            float mt = smax;
#pragma unroll
            for (int off = 16; off > 0; off >>= 1)
                mt = fmaxf(mt, __shfl_xor_sync(0xffffffffu, mt, off));
            float mnew = fmaxf(m, mt);
            float p = __expf(smax - mnew);    // 0 for masked lanes
            float psum = p;
#pragma unroll
            for (int off = 16; off > 0; off >>= 1)
                psum += __shfl_xor_sync(0xffffffffu, psum, off);
            float alpha = __expf(m - mnew);
            l = l * alpha + psum;
            m = mnew;
#pragma unroll
            for (int jj = 0; jj < 4; jj++) {
                acc4[jj].x *= alpha; acc4[jj].y *= alpha;
                acc4[jj].z *= alpha; acc4[jj].w *= alpha;
            }

            // ---- PV: gather selected V row per step ----
            for (int s = 0; s <= send; s++) {
                float pb = __shfl_sync(0xffffffffu, p, s);
                int   nb = __shfl_sync(0xffffffffu, nsel, s);
                const float4* vr4 = (const float4*)(vb + (size_t)(s0 + s) * QN + (size_t)nb * CC);
#pragma unroll
                for (int jj = 0; jj < 4; jj++) {
                    float4 vv = vr4[jj * 32 + lane];
                    acc4[jj].x += pb * vv.x; acc4[jj].y += pb * vv.y;
                    acc4[jj].z += pb * vv.z; acc4[jj].w += pb * vv.w;
                }
            }
        }
        __syncthreads();
    }

    float inv = 1.f / l;
    float4* yp4 = (float4*)(Y + (size_t)r * CC);
#pragma unroll
    for (int jj = 0; jj < 4; jj++)
        yp4[jj * 32 + lane] = make_float4(acc4[jj].x * inv, acc4[jj].y * inv,
                                          acc4[jj].z * inv, acc4[jj].w * inv);
}

// ---------------------------------------------------------------------------
extern "C" void kernel_launch(void* const* d_in, const int* in_sizes, int n_in,
                              void* d_out, int out_size)
{
    const float* a    = (const float*)d_in[0];
    const float* x    = (const float*)d_in[1];
    const float* Wq   = (const float*)d_in[2];
    const float* Wk   = (const float*)d_in[3];
    const float* Wv   = (const float*)d_in[4];
    const float* Wo   = (const float*)d_in[5];
    const float* cosT = (const float*)d_in[6];
    const float* sinT = (const float*)d_in[7];
    float* out = (float*)d_out;

    float* Qb; cudaGetSymbolAddress((void**)&Qb, g_Q);
    float* Kb; cudaGetSymbolAddress((void**)&Kb, g_K);
    float* Vb; cudaGetSymbolAddress((void**)&Vb, g_V);
    float* Yb; cudaGetSymbolAddress((void**)&Yb, g_Y);

    const int M = BB * TT;
    const float qscale = 0.04419417382415922f;  // 1/sqrt(512)

    const size_t attn_smem = 32 * KROW * sizeof(float4);   // 66,048 B
    cudaFuncSetAttribute((void*)attn_kernel,
                         cudaFuncAttributeMaxDynamicSharedMemorySize, (int)attn_smem);

    dim3 thr(256);
    gemm_kernel<1><<<dim3(QN / 64, M / 128), thr>>>(a, Wq, Qb, M, QN, CC, cosT, sinT, qscale);
    gemm_kernel<1><<<dim3(CC / 64, M / 128), thr>>>(x, Wk, Kb, M, CC, CC, cosT, sinT, 1.0f);
    gemm_kernel<0><<<dim3(QN / 64, M / 128), thr>>>(a, Wv, Vb, M, QN, CC, nullptr, nullptr, 1.0f);
    attn_kernel<<<M / 8, thr, attn_smem>>>(Qb, Kb, Vb, Yb);
    gemm_kernel<0><<<dim3(CC / 64, M / 128), thr>>>(Yb, Wo, out, M, CC, CC, nullptr, nullptr, 1.0f);
}

// round 10
// speedup vs baseline: 1.3461x; 1.3461x over previous
#include <cuda_runtime.h>
#include <math.h>

#define BB 2
#define TT 2048
#define CC 512
#define NB 4
#define QN (NB*CC)   // 2048
#define HALF (CC/2)  // 256

// Scratch (no cudaMalloc allowed)
__device__ float g_Q[BB*TT*QN];
__device__ float g_K[BB*TT*CC];
__device__ float g_V[BB*TT*QN];
__device__ float g_Y[BB*TT*CC];

// ---------------------------------------------------------------------------
// SGEMM (R1 scalar version, known-good): Out[M,N] = A[M,K] @ W[K,N].
// BM=128, BN=64, BK=16, 256 threads, 8x4 per thread. Optional RoPE + scale.
// ---------------------------------------------------------------------------
template<int DO_ROPE>
__global__ void __launch_bounds__(256) gemm_kernel(
    const float* __restrict__ A, const float* __restrict__ W, float* __restrict__ Out,
    int M, int N, int K,
    const float* __restrict__ cosT, const float* __restrict__ sinT, float scale)
{
    constexpr int BM = 128, BN = 64, BK = 16;
    __shared__ float As[BK][BM];
    __shared__ float Ws[BK][BN];

    const int tid = threadIdx.x;
    const int tx = tid & 15;
    const int ty = tid >> 4;
    const int rowBase = blockIdx.y * BM;
    const int colBase = blockIdx.x * BN;

    float acc[8][4];
#pragma unroll
    for (int m = 0; m < 8; m++)
#pragma unroll
        for (int n = 0; n < 4; n++) acc[m][n] = 0.f;

    for (int k0 = 0; k0 < K; k0 += BK) {
#pragma unroll
        for (int i = 0; i < 2; i++) {
            int slot = tid + i * 256;
            int r  = slot >> 2;
            int c4 = (slot & 3) * 4;
            float4 v = *(const float4*)(A + (size_t)(rowBase + r) * K + k0 + c4);
            As[c4 + 0][r] = v.x; As[c4 + 1][r] = v.y;
            As[c4 + 2][r] = v.z; As[c4 + 3][r] = v.w;
        }
        {
            int rr = tid >> 4;
            int c4 = (tid & 15) * 4;
            float4 v = *(const float4*)(W + (size_t)(k0 + rr) * N + colBase + c4);
            *(float4*)&Ws[rr][c4] = v;
        }
        __syncthreads();

#pragma unroll
        for (int kk = 0; kk < BK; kk++) {
            float4 a0 = *(float4*)&As[kk][ty * 8];
            float4 a1 = *(float4*)&As[kk][ty * 8 + 4];
            float4 wv = *(float4*)&Ws[kk][tx * 4];
            float ar[8] = {a0.x, a0.y, a0.z, a0.w, a1.x, a1.y, a1.z, a1.w};
            float wr[4] = {wv.x, wv.y, wv.z, wv.w};
#pragma unroll
            for (int m = 0; m < 8; m++)
#pragma unroll
                for (int n = 0; n < 4; n++) acc[m][n] += ar[m] * wr[n];
        }
        __syncthreads();
    }

    const int gc = colBase + tx * 4;
#pragma unroll
    for (int mI = 0; mI < 8; mI++) {
        int gr = rowBase + ty * 8 + mI;
        float o0 = acc[mI][0], o1 = acc[mI][1], o2 = acc[mI][2], o3 = acc[mI][3];
        if (DO_ROPE) {
            int t   = gr & (TT - 1);
            int cin = gc & (CC - 1);
            int i0  = cin >> 1;
            float c0v = cosT[t * HALF + i0],     s0v = sinT[t * HALF + i0];
            float c1v = cosT[t * HALF + i0 + 1], s1v = sinT[t * HALF + i0 + 1];
            float r0 = o0 * c0v - o1 * s0v;
            float r1 = o0 * s0v + o1 * c0v;
            float r2 = o2 * c1v - o3 * s1v;
            float r3 = o2 * s1v + o3 * c1v;
            o0 = r0; o1 = r1; o2 = r2; o3 = r3;
        }
        float4 out4 = make_float4(o0 * scale, o1 * scale, o2 * scale, o3 * scale);
        *(float4*)(Out + (size_t)gr * N + gc) = out4;
    }
}

// ---------------------------------------------------------------------------
// Fused routed attention: R1 structure (c-per-lane, 1 warp/row, 8 rows/CTA,
// K tile in smem) with three micro-opts:
//  (1) pair-fold warp reduce: 10 SHFL/step instead of 20, argmax built in
//  (2) conditional rescale: skip 16 FMUL + 1 MUFU unless a new max is set
//  (3) hoisted V pointer arithmetic
// ---------------------------------------------------------------------------
__global__ void __launch_bounds__(256) attn_kernel(
    const float* __restrict__ Q, const float* __restrict__ K,
    const float* __restrict__ V, float* __restrict__ Y)
{
    constexpr int SBLK = 16;
    __shared__ float4 ks[SBLK][CC / 4];   // 32KB

    const int tid  = threadIdx.x;
    const int w    = tid >> 5;
    const int lane = tid & 31;
    const int r    = blockIdx.x * 8 + w;
    const int t    = r & (TT - 1);
    const int tmax = (blockIdx.x * 8 + 7) & (TT - 1);

    float4 q[NB][4];
    const float* qp = Q + (size_t)r * QN;
#pragma unroll
    for (int n = 0; n < NB; n++)
#pragma unroll
        for (int jj = 0; jj < 4; jj++)
            q[n][jj] = *(const float4*)(qp + n * CC + jj * 128 + lane * 4);

    float4 acc[4];
#pragma unroll
    for (int jj = 0; jj < 4; jj++) acc[jj] = make_float4(0.f, 0.f, 0.f, 0.f);
    float m = -1e30f, l = 0.f;

    const float* kb = K + (size_t)(r - t) * CC;
    const float* vb = V + (size_t)(r - t) * QN;
    const int lane4 = lane * 4;
    const int b0 = lane & 1;          // pair-fold selectors (compile-time-ish)
    const int b1 = (lane >> 1) & 1;

    for (int s0 = 0; s0 <= tmax; s0 += SBLK) {
#pragma unroll
        for (int i = 0; i < 8; i++) {
            int slot = tid + i * 256;
            int si = slot >> 7, cj = slot & 127;
            ks[si][cj] = *(const float4*)(kb + (size_t)(s0 + si) * CC + cj * 4);
        }
        __syncthreads();

        const float* vs0 = vb + (size_t)s0 * QN;
        int send = t - s0; if (send > SBLK - 1) send = SBLK - 1;
        for (int si = 0; si <= send; si++) {
            float4 k4[4];
#pragma unroll
            for (int jj = 0; jj < 4; jj++) k4[jj] = ks[si][jj * 32 + lane];

            float d[NB];
#pragma unroll
            for (int n = 0; n < NB; n++) {
                float s = 0.f;
#pragma unroll
                for (int jj = 0; jj < 4; jj++) {
                    s += q[n][jj].x * k4[jj].x;
                    s += q[n][jj].y * k4[jj].y;
                    s += q[n][jj].z * k4[jj].z;
                    s += q[n][jj].w * k4[jj].w;
                }
                d[n] = s;
            }

            // ---- pair-fold reduction: 10 SHFL total ----
            // fold branches (0,1) and (2,3) across lane bit0
            float sel01  = b0 ? d[0] : d[1];
            float keep01 = b0 ? d[1] : d[0];
            float w01 = keep01 + __shfl_xor_sync(0xffffffffu, sel01, 1);
            float sel23  = b0 ? d[2] : d[3];
            float keep23 = b0 ? d[3] : d[2];
            float w23 = keep23 + __shfl_xor_sync(0xffffffffu, sel23, 1);
            // fold (w01, w23) across lane bit1
            float selq  = b1 ? w01 : w23;
            float keepq = b1 ? w23 : w01;
            float wv = keepq + __shfl_xor_sync(0xffffffffu, selq, 2);
            // reduce within branch class (lane&3 preserved by xor 4/8/16)
            wv += __shfl_xor_sync(0xffffffffu, wv, 4);
            wv += __shfl_xor_sync(0xffffffffu, wv, 8);
            wv += __shfl_xor_sync(0xffffffffu, wv, 16);
            // lane holds total score of branch (lane & 3)

            // ---- argmax exchange over the 4 branch classes ----
            float v  = wv;
            int   id = lane & 3;
#pragma unroll
            for (int off = 1; off <= 2; off <<= 1) {
                float v1 = __shfl_xor_sync(0xffffffffu, v, off);
                int  id1 = __shfl_xor_sync(0xffffffffu, id, off);
                if (v1 > v || (v1 == v && id1 < id)) { v = v1; id = id1; }
            }
            const float smax = v;      // warp-uniform
            const int   nsel = id;     // warp-uniform

            // ---- online softmax with conditional rescale ----
            if (smax > m) {            // warp-uniform branch (~8 hits per row)
                float alpha = __expf(m - smax);
                l *= alpha;
#pragma unroll
                for (int jj = 0; jj < 4; jj++) {
                    acc[jj].x *= alpha; acc[jj].y *= alpha;
                    acc[jj].z *= alpha; acc[jj].w *= alpha;
                }
                m = smax;
            }
            float p = __expf(smax - m);
            l += p;

            const float4* vr = (const float4*)(vs0 + (size_t)si * QN + (nsel << 9));
#pragma unroll
            for (int jj = 0; jj < 4; jj++) {
                float4 vv = vr[jj * 32 + lane];
                acc[jj].x += p * vv.x;
                acc[jj].y += p * vv.y;
                acc[jj].z += p * vv.z;
                acc[jj].w += p * vv.w;
            }
        }
        __syncthreads();
    }

    float inv = 1.f / l;
    float* yp = Y + (size_t)r * CC;
#pragma unroll
    for (int jj = 0; jj < 4; jj++) {
        float4 o = make_float4(acc[jj].x * inv, acc[jj].y * inv,
                               acc[jj].z * inv, acc[jj].w * inv);
        *(float4*)(yp + jj * 128 + lane4) = o;
    }
}

// ---------------------------------------------------------------------------
extern "C" void kernel_launch(void* const* d_in, const int* in_sizes, int n_in,
                              void* d_out, int out_size)
{
    const float* a    = (const float*)d_in[0];
    const float* x    = (const float*)d_in[1];
    const float* Wq   = (const float*)d_in[2];
    const float* Wk   = (const float*)d_in[3];
    const float* Wv   = (const float*)d_in[4];
    const float* Wo   = (const float*)d_in[5];
    const float* cosT = (const float*)d_in[6];
    const float* sinT = (const float*)d_in[7];
    float* out = (float*)d_out;

    float* Qb; cudaGetSymbolAddress((void**)&Qb, g_Q);
    float* Kb; cudaGetSymbolAddress((void**)&Kb, g_K);
    float* Vb; cudaGetSymbolAddress((void**)&Vb, g_V);
    float* Yb; cudaGetSymbolAddress((void**)&Yb, g_Y);

    const int M = BB * TT;
    const float qscale = 0.04419417382415922f;  // 1/sqrt(512)

    dim3 thr(256);
    gemm_kernel<1><<<dim3(QN / 64, M / 128), thr>>>(a, Wq, Qb, M, QN, CC, cosT, sinT, qscale);
    gemm_kernel<1><<<dim3(CC / 64, M / 128), thr>>>(x, Wk, Kb, M, CC, CC, cosT, sinT, 1.0f);
    gemm_kernel<0><<<dim3(QN / 64, M / 128), thr>>>(a, Wv, Vb, M, QN, CC, nullptr, nullptr, 1.0f);
    attn_kernel<<<M / 8, thr>>>(Qb, Kb, Vb, Yb);
    gemm_kernel<0><<<dim3(CC / 64, M / 128), thr>>>(Yb, Wo, out, M, CC, CC, nullptr, nullptr, 1.0f);
}

// round 11
// speedup vs baseline: 1.4698x; 1.0920x over previous
#include <cuda_runtime.h>
#include <math.h>

#define BB 2
#define TT 2048
#define CC 512
#define NB 4
#define QN (NB*CC)   // 2048
#define HALF (CC/2)  // 256

// Scratch (no cudaMalloc allowed)
__device__ float g_Q[BB*TT*QN];
__device__ float g_K[BB*TT*CC];
__device__ float g_V[BB*TT*QN];
__device__ float g_Y[BB*TT*CC];

// ---------------------------------------------------------------------------
// SGEMM (R1 scalar version, known-good): Out[M,N] = A[M,K] @ W[K,N].
// BM=128, BN=64, BK=16, 256 threads, 8x4 per thread. Optional RoPE + scale.
// ---------------------------------------------------------------------------
template<int DO_ROPE>
__global__ void __launch_bounds__(256) gemm_kernel(
    const float* __restrict__ A, const float* __restrict__ W, float* __restrict__ Out,
    int M, int N, int K,
    const float* __restrict__ cosT, const float* __restrict__ sinT, float scale)
{
    constexpr int BM = 128, BN = 64, BK = 16;
    __shared__ float As[BK][BM];
    __shared__ float Ws[BK][BN];

    const int tid = threadIdx.x;
    const int tx = tid & 15;
    const int ty = tid >> 4;
    const int rowBase = blockIdx.y * BM;
    const int colBase = blockIdx.x * BN;

    float acc[8][4];
#pragma unroll
    for (int m = 0; m < 8; m++)
#pragma unroll
        for (int n = 0; n < 4; n++) acc[m][n] = 0.f;

    for (int k0 = 0; k0 < K; k0 += BK) {
#pragma unroll
        for (int i = 0; i < 2; i++) {
            int slot = tid + i * 256;
            int r  = slot >> 2;
            int c4 = (slot & 3) * 4;
            float4 v = *(const float4*)(A + (size_t)(rowBase + r) * K + k0 + c4);
            As[c4 + 0][r] = v.x; As[c4 + 1][r] = v.y;
            As[c4 + 2][r] = v.z; As[c4 + 3][r] = v.w;
        }
        {
            int rr = tid >> 4;
            int c4 = (tid & 15) * 4;
            float4 v = *(const float4*)(W + (size_t)(k0 + rr) * N + colBase + c4);
            *(float4*)&Ws[rr][c4] = v;
        }
        __syncthreads();

#pragma unroll
        for (int kk = 0; kk < BK; kk++) {
            float4 a0 = *(float4*)&As[kk][ty * 8];
            float4 a1 = *(float4*)&As[kk][ty * 8 + 4];
            float4 wv = *(float4*)&Ws[kk][tx * 4];
            float ar[8] = {a0.x, a0.y, a0.z, a0.w, a1.x, a1.y, a1.z, a1.w};
            float wr[4] = {wv.x, wv.y, wv.z, wv.w};
#pragma unroll
            for (int m = 0; m < 8; m++)
#pragma unroll
                for (int n = 0; n < 4; n++) acc[m][n] += ar[m] * wr[n];
        }
        __syncthreads();
    }

    const int gc = colBase + tx * 4;
#pragma unroll
    for (int mI = 0; mI < 8; mI++) {
        int gr = rowBase + ty * 8 + mI;
        float o0 = acc[mI][0], o1 = acc[mI][1], o2 = acc[mI][2], o3 = acc[mI][3];
        if (DO_ROPE) {
            int t   = gr & (TT - 1);
            int cin = gc & (CC - 1);
            int i0  = cin >> 1;
            float c0v = cosT[t * HALF + i0],     s0v = sinT[t * HALF + i0];
            float c1v = cosT[t * HALF + i0 + 1], s1v = sinT[t * HALF + i0 + 1];
            float r0 = o0 * c0v - o1 * s0v;
            float r1 = o0 * s0v + o1 * c0v;
            float r2 = o2 * c1v - o3 * s1v;
            float r3 = o2 * s1v + o3 * c1v;
            o0 = r0; o1 = r1; o2 = r2; o3 = r3;
        }
        float4 out4 = make_float4(o0 * scale, o1 * scale, o2 * scale, o3 * scale);
        *(float4*)(Out + (size_t)gr * N + gc) = out4;
    }
}

// ---------------------------------------------------------------------------
// Fused routed attention: R10 structure (c-per-lane, pair-fold reduce,
// conditional rescale) + SOFTWARE-PIPELINED V LOAD: step i's V row is loaded
// while step i+1's dots execute, hiding the L2 latency on the serial chain.
// ---------------------------------------------------------------------------
__global__ void __launch_bounds__(256, 2) attn_kernel(
    const float* __restrict__ Q, const float* __restrict__ K,
    const float* __restrict__ V, float* __restrict__ Y)
{
    constexpr int SBLK = 16;
    __shared__ float4 ks[SBLK][CC / 4];   // 32KB

    const int tid  = threadIdx.x;
    const int w    = tid >> 5;
    const int lane = tid & 31;
    const int r    = blockIdx.x * 8 + w;
    const int t    = r & (TT - 1);
    const int tmax = (blockIdx.x * 8 + 7) & (TT - 1);

    float4 q[NB][4];
    const float* qp = Q + (size_t)r * QN;
#pragma unroll
    for (int n = 0; n < NB; n++)
#pragma unroll
        for (int jj = 0; jj < 4; jj++)
            q[n][jj] = *(const float4*)(qp + n * CC + jj * 128 + lane * 4);

    float4 acc[4];
#pragma unroll
    for (int jj = 0; jj < 4; jj++) acc[jj] = make_float4(0.f, 0.f, 0.f, 0.f);
    float m = -1e30f, l = 0.f;

    const float* kb = K + (size_t)(r - t) * CC;
    const float* vb = V + (size_t)(r - t) * QN;
    const int b0 = lane & 1;
    const int b1 = (lane >> 1) & 1;

    // score for step si of the current tile (dots + pair-fold + argmax)
    auto score = [&](int si, float& smax, int& nsel) {
        float4 k4[4];
#pragma unroll
        for (int jj = 0; jj < 4; jj++) k4[jj] = ks[si][jj * 32 + lane];
        float d[NB];
#pragma unroll
        for (int n = 0; n < NB; n++) {
            float s = 0.f;
#pragma unroll
            for (int jj = 0; jj < 4; jj++) {
                s += q[n][jj].x * k4[jj].x;
                s += q[n][jj].y * k4[jj].y;
                s += q[n][jj].z * k4[jj].z;
                s += q[n][jj].w * k4[jj].w;
            }
            d[n] = s;
        }
        // pair-fold reduction (10 SHFL), then argmax exchange (4 SHFL)
        float sel01  = b0 ? d[0] : d[1];
        float keep01 = b0 ? d[1] : d[0];
        float w01 = keep01 + __shfl_xor_sync(0xffffffffu, sel01, 1);
        float sel23  = b0 ? d[2] : d[3];
        float keep23 = b0 ? d[3] : d[2];
        float w23 = keep23 + __shfl_xor_sync(0xffffffffu, sel23, 1);
        float selq  = b1 ? w01 : w23;
        float keepq = b1 ? w23 : w01;
        float wv = keepq + __shfl_xor_sync(0xffffffffu, selq, 2);
        wv += __shfl_xor_sync(0xffffffffu, wv, 4);
        wv += __shfl_xor_sync(0xffffffffu, wv, 8);
        wv += __shfl_xor_sync(0xffffffffu, wv, 16);
        float v  = wv;
        int   id = lane & 3;
#pragma unroll
        for (int off = 1; off <= 2; off <<= 1) {
            float v1 = __shfl_xor_sync(0xffffffffu, v, off);
            int  id1 = __shfl_xor_sync(0xffffffffu, id, off);
            if (v1 > v || (v1 == v && id1 < id)) { v = v1; id = id1; }
        }
        smax = v; nsel = id;   // warp-uniform
    };

    for (int s0 = 0; s0 <= tmax; s0 += SBLK) {
#pragma unroll
        for (int i = 0; i < 8; i++) {
            int slot = tid + i * 256;
            int si = slot >> 7, cj = slot & 127;
            ks[si][cj] = *(const float4*)(kb + (size_t)(s0 + si) * CC + cj * 4);
        }
        __syncthreads();

        const float* vs0 = vb + (size_t)s0 * QN;
        int send = t - s0; if (send > SBLK - 1) send = SBLK - 1;

        if (send >= 0) {
            // ---- prologue: score step 0, issue its V load ----
            float smax; int nsel;
            score(0, smax, nsel);
            if (smax > m) {
                float alpha = __expf(m - smax);
                l *= alpha;
#pragma unroll
                for (int jj = 0; jj < 4; jj++) {
                    acc[jj].x *= alpha; acc[jj].y *= alpha;
                    acc[jj].z *= alpha; acc[jj].w *= alpha;
                }
                m = smax;
            }
            float p_cur = __expf(smax - m);
            const float4* vr = (const float4*)(vs0 + (nsel << 9));
            float4 vv[4];
#pragma unroll
            for (int jj = 0; jj < 4; jj++) vv[jj] = vr[jj * 32 + lane];

            // ---- steady state: dots(i+1) overlap V(i) in flight ----
            for (int si = 1; si <= send; si++) {
                float smax2; int nsel2;
                score(si, smax2, nsel2);          // independent of acc/m/l
                // consume step si-1 (acc at scale m_{si-1}; p_cur matches)
                l += p_cur;
#pragma unroll
                for (int jj = 0; jj < 4; jj++) {
                    acc[jj].x += p_cur * vv[jj].x;
                    acc[jj].y += p_cur * vv[jj].y;
                    acc[jj].z += p_cur * vv[jj].z;
                    acc[jj].w += p_cur * vv[jj].w;
                }
                // now apply step si's rescale + issue its V load
                if (smax2 > m) {
                    float alpha = __expf(m - smax2);
                    l *= alpha;
#pragma unroll
                    for (int jj = 0; jj < 4; jj++) {
                        acc[jj].x *= alpha; acc[jj].y *= alpha;
                        acc[jj].z *= alpha; acc[jj].w *= alpha;
                    }
                    m = smax2;
                }
                p_cur = __expf(smax2 - m);
                vr = (const float4*)(vs0 + (size_t)si * QN + (nsel2 << 9));
#pragma unroll
                for (int jj = 0; jj < 4; jj++) vv[jj] = vr[jj * 32 + lane];
            }

            // ---- epilogue: consume last step ----
            l += p_cur;
#pragma unroll
            for (int jj = 0; jj < 4; jj++) {
                acc[jj].x += p_cur * vv[jj].x;
                acc[jj].y += p_cur * vv[jj].y;
                acc[jj].z += p_cur * vv[jj].z;
                acc[jj].w += p_cur * vv[jj].w;
            }
        }
        __syncthreads();
    }

    float inv = 1.f / l;
    float* yp = Y + (size_t)r * CC;
#pragma unroll
    for (int jj = 0; jj < 4; jj++) {
        float4 o = make_float4(acc[jj].x * inv, acc[jj].y * inv,
                               acc[jj].z * inv, acc[jj].w * inv);
        *(float4*)(yp + jj * 128 + lane * 4) = o;
    }
}

// ---------------------------------------------------------------------------
extern "C" void kernel_launch(void* const* d_in, const int* in_sizes, int n_in,
                              void* d_out, int out_size)
{
    const float* a    = (const float*)d_in[0];
    const float* x    = (const float*)d_in[1];
    const float* Wq   = (const float*)d_in[2];
    const float* Wk   = (const float*)d_in[3];
    const float* Wv   = (const float*)d_in[4];
    const float* Wo   = (const float*)d_in[5];
    const float* cosT = (const float*)d_in[6];
    const float* sinT = (const float*)d_in[7];
    float* out = (float*)d_out;

    float* Qb; cudaGetSymbolAddress((void**)&Qb, g_Q);
    float* Kb; cudaGetSymbolAddress((void**)&Kb, g_K);
    float* Vb; cudaGetSymbolAddress((void**)&Vb, g_V);
    float* Yb; cudaGetSymbolAddress((void**)&Yb, g_Y);

    const int M = BB * TT;
    const float qscale = 0.04419417382415922f;  // 1/sqrt(512)

    dim3 thr(256);
    gemm_kernel<1><<<dim3(QN / 64, M / 128), thr>>>(a, Wq, Qb, M, QN, CC, cosT, sinT, qscale);
    gemm_kernel<1><<<dim3(CC / 64, M / 128), thr>>>(x, Wk, Kb, M, CC, CC, cosT, sinT, 1.0f);
    gemm_kernel<0><<<dim3(QN / 64, M / 128), thr>>>(a, Wv, Vb, M, QN, CC, nullptr, nullptr, 1.0f);
    attn_kernel<<<M / 8, thr>>>(Qb, Kb, Vb, Yb);
    gemm_kernel<0><<<dim3(CC / 64, M / 128), thr>>>(Yb, Wo, out, M, CC, CC, nullptr, nullptr, 1.0f);
}